// round 15
// baseline (speedup 1.0000x reference)
#include <cuda_runtime.h>
#include <cuda_bf16.h>
#include <cstdint>

// ---------------- problem constants ----------------
#define D     768
#define T     8192
#define NREF  16384
#define C     96

// ---------------- match-kernel tiling ----------------
#define TM_CTA   128
#define TN_SUB   128               // n-subtile width
#define NSPLIT   16                // grid.y; each CTA covers NREF/NSPLIT = 1024 n
#define SUBTILES 8                 // 1024 / 128
#define KC       32                // K elems per half-stage
#define NHALF    (D / KC)          // 24 half-stages
#define TTILES   (T / TM_CTA)      // 64
#define CANDS    (NSPLIT * 4)      // 64 candidates per token

#define NEG_INF (-3.402823466e38f)

// smem layout (bytes)
// [0, 98304)        : bf16 buffers Ah/Am/Al/Bh/Bm/Bl, 16KB each.
//                     Row = 128B = 64 k (chunks 0-3 = even half, 4-7 = odd half).
// [98304, 196608)   : 3 fp32 staging bufs x 32KB (A 16KB + B 16KB), KC=32 each
// [196608, 197120)  : Sn (128 floats inv-norms)
// epilogue reuses [0, 66048) as 128 x 129 float score buffer
#define SM_AH      0u
#define SM_AM      16384u
#define SM_AL      32768u
#define SM_BH      49152u
#define SM_BM      65536u
#define SM_BL      81920u
#define SM_F32     98304u
#define SM_F32_STRIDE 32768u
#define SM_SN      196608u
#define SMEM_BYTES 197120u
#define BUF_STRIDE 129

// ---------------- device scratch (10.4 MB; proven-safe footprint) ----------------
__device__ float g_inv_rnorm[NREF];                    // 64 KB
__device__ float g_P[(size_t)C * NREF];                // 6.3 MB
__device__ float g_cand_val[(size_t)T * CANDS];        // 2 MB
__device__ int   g_cand_idx[(size_t)T * CANDS];        // 2 MB

// ---------------- PTX helpers (sm_80-era, compute_100-safe) ----------------
__device__ __forceinline__ void cpasync16(uint32_t s, const void* g) {
    asm volatile("cp.async.cg.shared.global [%0], [%1], 16;"
                 :: "r"(s), "l"(g) : "memory");
}
__device__ __forceinline__ void cp_commit() {
    asm volatile("cp.async.commit_group;" ::: "memory");
}
template <int N>
__device__ __forceinline__ void cp_wait() {
    asm volatile("cp.async.wait_group %0;" :: "n"(N) : "memory");
}
__device__ __forceinline__ void ldsm4(uint32_t* r, uint32_t addr) {
    asm volatile("ldmatrix.sync.aligned.m8n8.x4.shared.b16 {%0,%1,%2,%3}, [%4];"
        : "=r"(r[0]), "=r"(r[1]), "=r"(r[2]), "=r"(r[3]) : "r"(addr));
}
__device__ __forceinline__ void ldsm2(uint32_t* r, uint32_t addr) {
    asm volatile("ldmatrix.sync.aligned.m8n8.x2.shared.b16 {%0,%1}, [%2];"
        : "=r"(r[0]), "=r"(r[1]) : "r"(addr));
}
__device__ __forceinline__ void mma_bf16(float* d, const uint32_t* a, const uint32_t* b) {
    asm volatile(
        "mma.sync.aligned.m16n8k16.row.col.f32.bf16.bf16.f32 "
        "{%0,%1,%2,%3}, {%4,%5,%6,%7}, {%8,%9}, {%0,%1,%2,%3};"
        : "+f"(d[0]), "+f"(d[1]), "+f"(d[2]), "+f"(d[3])
        : "r"(a[0]), "r"(a[1]), "r"(a[2]), "r"(a[3]), "r"(b[0]), "r"(b[1]));
}

// ============================================================
// Prologue 1: inverse L2 norms of lut columns (fp32)
// ============================================================
__global__ void norm_kernel(const float* __restrict__ lut) {
    int n = blockIdx.x * blockDim.x + threadIdx.x;
    float s = 0.f;
#pragma unroll 8
    for (int d = 0; d < D; ++d) {
        float v = lut[(size_t)d * NREF + n];
        s = fmaf(v, v, s);
    }
    g_inv_rnorm[n] = 1.0f / sqrtf(s);
}

// ============================================================
// Prologue 2: P = W @ lut  (96 x 16384), fp32, 8 channels/thread
// ============================================================
__global__ void proj_lut_kernel(const float* __restrict__ lut,
                                const float* __restrict__ w) {
    int n  = blockIdx.x * 128 + threadIdx.x;
    int c0 = blockIdx.y * 8;
    float a[8] = {0, 0, 0, 0, 0, 0, 0, 0};
#pragma unroll 4
    for (int d = 0; d < D; ++d) {
        float l = lut[(size_t)d * NREF + n];
#pragma unroll
        for (int c = 0; c < 8; ++c)
            a[c] = fmaf(w[(c0 + c) * D + d], l, a[c]);
    }
#pragma unroll
    for (int c = 0; c < 8; ++c)
        g_P[(size_t)(c0 + c) * NREF + n] = a[c];
}

// ============================================================
// top-4 helpers (strict >: earliest/lowest index wins ties, matching jax)
// ============================================================
__device__ __forceinline__ void insert4(float* v, int* ix, float s, int n) {
    if (s > v[3]) {
        if (s > v[0]) {
            v[3]=v[2]; ix[3]=ix[2]; v[2]=v[1]; ix[2]=ix[1];
            v[1]=v[0]; ix[1]=ix[0]; v[0]=s;    ix[0]=n;
        } else if (s > v[1]) {
            v[3]=v[2]; ix[3]=ix[2]; v[2]=v[1]; ix[2]=ix[1];
            v[1]=s;    ix[1]=n;
        } else if (s > v[2]) {
            v[3]=v[2]; ix[3]=ix[2]; v[2]=s; ix[2]=n;
        } else { v[3]=s; ix[3]=n; }
    }
}
__device__ __forceinline__ void insert4u(unsigned long long* v, unsigned long long k) {
    if (k > v[3]) {
        if (k > v[0])      { v[3]=v[2]; v[2]=v[1]; v[1]=v[0]; v[0]=k; }
        else if (k > v[1]) { v[3]=v[2]; v[2]=v[1]; v[1]=k; }
        else if (k > v[2]) { v[3]=v[2]; v[2]=k; }
        else               { v[3]=k; }
    }
}

// ============================================================
// Exact 3-way bf16 decomposition of an fp32 pair, packed bf16x2.
// x = h + m + l exactly (24 mantissa bits = 3 x 8).
// ============================================================
__device__ __forceinline__ void split3_pair(float f0, float f1,
                                            uint32_t& hu, uint32_t& mu, uint32_t& lu) {
    uint32_t h0 = __float_as_uint(f0) & 0xFFFF0000u;
    uint32_t h1 = __float_as_uint(f1) & 0xFFFF0000u;
    hu = __byte_perm(h0, h1, 0x7632);
    float r10 = f0 - __uint_as_float(h0);      // exact
    float r11 = f1 - __uint_as_float(h1);
    uint32_t m0 = __float_as_uint(r10) & 0xFFFF0000u;
    uint32_t m1 = __float_as_uint(r11) & 0xFFFF0000u;
    mu = __byte_perm(m0, m1, 0x7632);
    float r20 = r10 - __uint_as_float(m0);     // exact, <=8 significant bits
    float r21 = r11 - __uint_as_float(m1);
    lu = __byte_perm(__float_as_uint(r20), __float_as_uint(r21), 0x7632);
}

// ============================================================
// Main: half-stage pipelined (conv(p+1) overlaps mma(p), disjoint chunk
// halves, ONE barrier per half-iter), 6-pass GEMM + running top-4.
// grid (TTILES=64, NSPLIT=16); 256 threads, 8 warps (2M x 4N), warp 64x32.
// ============================================================
__global__ __launch_bounds__(256, 1)
void match_kernel(const float* __restrict__ x, const float* __restrict__ lut) {
    extern __shared__ __align__(16) char smraw[];
    uint32_t smb;
    asm("{ .reg .u64 t; cvta.to.shared.u64 t, %1; cvt.u32.u64 %0, t; }"
        : "=r"(smb) : "l"(smraw));

    const int tid  = threadIdx.x;
    const int lane = tid & 31;
    const int wid  = tid >> 5;
    const int wm   = wid >> 2;       // 0..1
    const int wn   = wid & 3;        // 0..3
    const int t0   = blockIdx.x * TM_CTA;
    const int nb0  = blockIdx.y * (NREF / NSPLIT);

    // conversion mapping: token/row ct (0..127), chunk-half ch (0/1)
    const int ct = tid & 127;
    const int ch = tid >> 7;

    // ldmatrix lane mappings (hardware-validated rounds 10-12)
    const int arow = lane & 15;
    const int akb  = lane >> 4;
    const int ar7  = arow & 7;
    const int brow = lane & 7;
    const int bkb  = (lane >> 3) & 1;
    const uint32_t aRowOff = (uint32_t)((wm * 64 + arow) * 128);
    const uint32_t bRowOff = (uint32_t)((wn * 32 + brow) * 128);

    float* Sn = (float*)(smraw + SM_SN);

    // running top-4 across all subtiles (owned by threads 0..127)
    float topv[4] = {NEG_INF, NEG_INF, NEG_INF, NEG_INF};
    int   topi[4] = {0, 0, 0, 0};

#pragma unroll 1
    for (int st = 0; st < SUBTILES; ++st) {
        const int nb = nb0 + st * TN_SUB;
        if (tid < TN_SUB) Sn[tid] = g_inv_rnorm[nb + tid];

        float acc[4][4][4];
#pragma unroll
        for (int mt = 0; mt < 4; ++mt)
#pragma unroll
            for (int nt = 0; nt < 4; ++nt)
#pragma unroll
                for (int q = 0; q < 4; ++q) acc[mt][nt][q] = 0.f;

        // ---- half-stage fp32 loader: k-range [p*32, p*32+32) ----
        auto load_half = [&](int p) {
            const uint32_t dst = smb + SM_F32 + (uint32_t)(p % 3) * SM_F32_STRIDE;
            const int d0 = p * KC;
            const float* xs = x   + (size_t)d0 * T    + t0;
            const float* ls = lut + (size_t)d0 * NREF + nb;
#pragma unroll
            for (int i = 0; i < 4; ++i) {
                const int id = tid + i * 256;
                const int r = id >> 5, cq = id & 31;
                cpasync16(dst + (uint32_t)(r * 512 + cq * 16),
                          xs + (size_t)r * T + cq * 4);
            }
#pragma unroll
            for (int i = 0; i < 4; ++i) {
                const int id = tid + i * 256;
                const int r = id >> 5, cq = id & 31;
                cpasync16(dst + 16384u + (uint32_t)(r * 512 + cq * 16),
                          ls + (size_t)r * NREF + cq * 4);
            }
            cp_commit();
        };

        // ---- convert half p: fp32 buf (p%3) -> bf16 chunks (p&1)*4 .. +3 ----
        auto convert_half = [&](int p) {
            const float* Af = (const float*)(smraw + SM_F32 + (size_t)(p % 3) * SM_F32_STRIDE);
            const float* Bf = Af + 4096;   // +16KB
            const int h4 = (p & 1) * 4;
#pragma unroll
            for (int cc = 0; cc < 2; ++cc) {
                const int cl = ch * 2 + cc;             // local chunk 0..3
                const uint32_t pos = (uint32_t)(ct * 128 +
                                     (((h4 + cl) ^ (ct & 7)) << 4));
                uint32_t h[4], m[4], l[4];
#pragma unroll
                for (int p4 = 0; p4 < 4; ++p4) {
                    const int k = cl * 8 + 2 * p4;      // local k in [0,32)
                    split3_pair(Af[k * 128 + ct], Af[(k + 1) * 128 + ct],
                                h[p4], m[p4], l[p4]);
                }
                *(uint4*)(smraw + SM_AH + pos) = make_uint4(h[0], h[1], h[2], h[3]);
                *(uint4*)(smraw + SM_AM + pos) = make_uint4(m[0], m[1], m[2], m[3]);
                *(uint4*)(smraw + SM_AL + pos) = make_uint4(l[0], l[1], l[2], l[3]);
#pragma unroll
                for (int p4 = 0; p4 < 4; ++p4) {
                    const int k = cl * 8 + 2 * p4;
                    split3_pair(Bf[k * 128 + ct], Bf[(k + 1) * 128 + ct],
                                h[p4], m[p4], l[p4]);
                }
                *(uint4*)(smraw + SM_BH + pos) = make_uint4(h[0], h[1], h[2], h[3]);
                *(uint4*)(smraw + SM_BM + pos) = make_uint4(m[0], m[1], m[2], m[3]);
                *(uint4*)(smraw + SM_BL + pos) = make_uint4(l[0], l[1], l[2], l[3]);
            }
        };

        // ---- mma on half p: chunks (p&1)*4 + {0..3}, 6 passes ----
        auto mma_half = [&](int p) {
            const int h4 = (p & 1) * 4;
#pragma unroll
            for (int ks = 0; ks < 2; ++ks) {
                const uint32_t ac = (uint32_t)(((h4 + ks * 2 + akb) ^ ar7) * 16);
                const uint32_t bc = (uint32_t)(((h4 + ks * 2 + bkb) ^ brow) * 16);
                uint32_t a_op[4][4];
                uint32_t bh[4][2], bm[4][2], bl[4][2];

#pragma unroll
                for (int nt = 0; nt < 4; ++nt) {
                    ldsm2(bh[nt], smb + SM_BH + bRowOff + nt * 1024 + bc);
                    ldsm2(bm[nt], smb + SM_BM + bRowOff + nt * 1024 + bc);
                    ldsm2(bl[nt], smb + SM_BL + bRowOff + nt * 1024 + bc);
                }

                // A = h : hh, hm, hl
#pragma unroll
                for (int mt = 0; mt < 4; ++mt)
                    ldsm4(a_op[mt], smb + SM_AH + aRowOff + mt * 2048 + ac);
#pragma unroll
                for (int mt = 0; mt < 4; ++mt)
#pragma unroll
                    for (int nt = 0; nt < 4; ++nt)
                        mma_bf16(acc[mt][nt], a_op[mt], bh[nt]);
#pragma unroll
                for (int mt = 0; mt < 4; ++mt)
#pragma unroll
                    for (int nt = 0; nt < 4; ++nt)
                        mma_bf16(acc[mt][nt], a_op[mt], bm[nt]);
#pragma unroll
                for (int mt = 0; mt < 4; ++mt)
#pragma unroll
                    for (int nt = 0; nt < 4; ++nt)
                        mma_bf16(acc[mt][nt], a_op[mt], bl[nt]);

                // A = m : mh, mm
#pragma unroll
                for (int mt = 0; mt < 4; ++mt)
                    ldsm4(a_op[mt], smb + SM_AM + aRowOff + mt * 2048 + ac);
#pragma unroll
                for (int mt = 0; mt < 4; ++mt)
#pragma unroll
                    for (int nt = 0; nt < 4; ++nt)
                        mma_bf16(acc[mt][nt], a_op[mt], bh[nt]);
#pragma unroll
                for (int mt = 0; mt < 4; ++mt)
#pragma unroll
                    for (int nt = 0; nt < 4; ++nt)
                        mma_bf16(acc[mt][nt], a_op[mt], bm[nt]);

                // A = l : lh
#pragma unroll
                for (int mt = 0; mt < 4; ++mt)
                    ldsm4(a_op[mt], smb + SM_AL + aRowOff + mt * 2048 + ac);
#pragma unroll
                for (int mt = 0; mt < 4; ++mt)
#pragma unroll
                    for (int nt = 0; nt < 4; ++nt)
                        mma_bf16(acc[mt][nt], a_op[mt], bh[nt]);
            }
        };

        // ---- pipeline prologue: loads 0..2, convert half 0 ----
        load_half(0);
        load_half(1);
        load_half(2);
        cp_wait<1>();      // loads 0,1 arrived (this thread)
        __syncthreads();   // arrivals visible CTA-wide
        convert_half(0);
        __syncthreads();   // bf16 half 0 ready

        // ---- main pipeline: ONE barrier per half-iter ----
#pragma unroll 1
        for (int p = 0; p < NHALF; ++p) {
            mma_half(p);                       // reads chunks (p&1)*4..
            if (p + 1 < NHALF)
                convert_half(p + 1);           // writes chunks ((p+1)&1)*4.. (disjoint)
            if (p + 3 < NHALF) {
                load_half(p + 3);
                cp_wait<1>();                  // load(p+2) arrived
            } else {
                cp_wait<0>();
            }
            __syncthreads();                   // publish conv(p+1) + cp.async arrivals
        }

        // ---- subtile epilogue: scale + update running top-4 ----
        float* buf = (float*)smraw;            // reuse bf16 region: 128 x BUF_STRIDE
        const int r0 = wm * 64 + (lane >> 2);
        const int cb = wn * 32 + 2 * (lane & 3);
#pragma unroll
        for (int mt = 0; mt < 4; ++mt)
#pragma unroll
            for (int nt = 0; nt < 4; ++nt) {
                const int rr = r0 + mt * 16;
                const int cc = cb + nt * 8;
                const float s0 = Sn[cc], s1 = Sn[cc + 1];
                buf[rr * BUF_STRIDE + cc]           = acc[mt][nt][0] * s0;
                buf[rr * BUF_STRIDE + cc + 1]       = acc[mt][nt][1] * s1;
                buf[(rr + 8) * BUF_STRIDE + cc]     = acc[mt][nt][2] * s0;
                buf[(rr + 8) * BUF_STRIDE + cc + 1] = acc[mt][nt][3] * s1;
            }
        __syncthreads();

        if (tid < TM_CTA) {
            const float* row = buf + tid * BUF_STRIDE;
#pragma unroll 4
            for (int cc = 0; cc < TN_SUB; ++cc)
                insert4(topv, topi, row[cc], nb + cc);
        }
        __syncthreads();   // scan done before next subtile overwrites smem
    }

    // ---- final: 4 candidates per (token, split) ----
    if (tid < TM_CTA) {
        const size_t base = ((size_t)(t0 + tid) * NSPLIT + blockIdx.y) * 4;
#pragma unroll
        for (int j = 0; j < 4; ++j) {
            g_cand_val[base + j] = topv[j];
            g_cand_idx[base + j] = topi[j];
        }
    }
}

// ============================================================
// Merge 64 candidates/token -> top-4 (warp per token, u64 keys),
// then out[c,t] = 0.25 * sum_k P[c, idx_k] + b[c].
// grid T/4 blocks, 128 threads.
// ============================================================
__global__ __launch_bounds__(128, 1)
void merge_project_kernel(const float* __restrict__ bias,
                          float* __restrict__ out) {
    __shared__ int sel[4][4];
    const int w = threadIdx.x >> 5, lane = threadIdx.x & 31;
    const int t = blockIdx.x * 4 + w;

    const float* vb = g_cand_val + (size_t)t * CANDS;
    const int*   ib = g_cand_idx + (size_t)t * CANDS;

    unsigned long long best[4] = {0, 0, 0, 0};
#pragma unroll
    for (int j = 0; j < CANDS / 32; ++j) {
        const int e = lane + j * 32;
        uint32_t u = __float_as_uint(vb[e]);
        u ^= (u & 0x80000000u) ? 0xFFFFFFFFu : 0x80000000u;
        unsigned long long key =
            ((unsigned long long)u << 32) | (uint32_t)(0x7FFFFFFF - ib[e]);
        insert4u(best, key);
    }
#pragma unroll
    for (int off = 16; off; off >>= 1) {
        unsigned long long o0 = __shfl_xor_sync(0xFFFFFFFFu, best[0], off);
        unsigned long long o1 = __shfl_xor_sync(0xFFFFFFFFu, best[1], off);
        unsigned long long o2 = __shfl_xor_sync(0xFFFFFFFFu, best[2], off);
        unsigned long long o3 = __shfl_xor_sync(0xFFFFFFFFu, best[3], off);
        insert4u(best, o0); insert4u(best, o1);
        insert4u(best, o2); insert4u(best, o3);
    }
    if (lane < 4) sel[w][lane] = 0x7FFFFFFF - (int)(uint32_t)best[lane];
    __syncthreads();

    for (int i = threadIdx.x; i < 4 * C; i += 128) {
        const int cch = i % C;
        const int tw  = i / C;
        const float* Pr = g_P + (size_t)cch * NREF;
        const int* s = sel[tw];
        float o = 0.25f * (Pr[s[0]] + Pr[s[1]] + Pr[s[2]] + Pr[s[3]]);
        out[(size_t)cch * T + (blockIdx.x * 4 + tw)] = o + bias[cch];
    }
}

// ============================================================
extern "C" void kernel_launch(void* const* d_in, const int* in_sizes, int n_in,
                              void* d_out, int out_size) {
    const float* x    = (const float*)d_in[0];   // [1, 768, 8192]
    const float* lut  = (const float*)d_in[1];   // [1, 768, 16384]
    const float* w    = (const float*)d_in[2];   // [96, 768]
    const float* bias = (const float*)d_in[3];   // [96]
    float* out = (float*)d_out;                  // [1, 96, 8192]

    cudaFuncSetAttribute(match_kernel,
                         cudaFuncAttributeMaxDynamicSharedMemorySize,
                         SMEM_BYTES);

    norm_kernel<<<NREF / 256, 256>>>(lut);
    proj_lut_kernel<<<dim3(NREF / 128, C / 8), 128>>>(lut, w);
    match_kernel<<<dim3(TTILES, NSPLIT), 256, SMEM_BYTES>>>(x, lut);
    merge_project_kernel<<<T / 4, 128>>>(bias, out);
}

// round 16
// speedup vs baseline: 1.0343x; 1.0343x over previous
#include <cuda_runtime.h>
#include <cuda_bf16.h>
#include <cstdint>

// ---------------- problem constants ----------------
#define D     768
#define T     8192
#define NREF  16384
#define C     96

// ---------------- match-kernel tiling ----------------
#define TM_CTA   128
#define TN_SUB   128               // n-subtile width
#define NSPLIT   16                // grid.y; each CTA covers NREF/NSPLIT = 1024 n
#define SUBTILES 8                 // 1024 / 128
#define KC       64                // K elems per stage
#define NITER    (D / KC)          // 12
#define TTILES   (T / TM_CTA)      // 64
#define CANDS    (NSPLIT * 4)      // 64 candidates per token
#define NTHREADS 512

#define NEG_INF (-3.402823466e38f)

// smem layout (bytes) — identical regions to round 12 (validated):
// [0, 98304)        : bf16 bufs Ah/Am/Al/Bh/Bm/Bl, 16KB each (128B rows, XOR swizzle)
// [98304, 229376)   : 2 fp32 stages x 64KB (A 32KB + B 32KB)
// [229376, 229888)  : Sn (128 floats)
// epilogue reuses [0, 66048) as 128 x 129 float score buffer
#define SM_AH      0u
#define SM_AM      16384u
#define SM_AL      32768u
#define SM_BH      49152u
#define SM_BM      65536u
#define SM_BL      81920u
#define SM_F32     98304u
#define SM_F32_STRIDE 65536u
#define SM_SN      229376u
#define SMEM_BYTES 229888u
#define BUF_STRIDE 129

// ---------------- device scratch (10.4 MB; proven-safe footprint) ----------------
__device__ float g_inv_rnorm[NREF];                    // 64 KB
__device__ float g_P[(size_t)C * NREF];                // 6.3 MB
__device__ float g_cand_val[(size_t)T * CANDS];        // 2 MB
__device__ int   g_cand_idx[(size_t)T * CANDS];        // 2 MB

// ---------------- PTX helpers (sm_80-era, compute_100-safe) ----------------
__device__ __forceinline__ void cpasync16(uint32_t s, const void* g) {
    asm volatile("cp.async.cg.shared.global [%0], [%1], 16;"
                 :: "r"(s), "l"(g) : "memory");
}
__device__ __forceinline__ void cp_commit() {
    asm volatile("cp.async.commit_group;" ::: "memory");
}
template <int N>
__device__ __forceinline__ void cp_wait() {
    asm volatile("cp.async.wait_group %0;" :: "n"(N) : "memory");
}
__device__ __forceinline__ void ldsm4(uint32_t* r, uint32_t addr) {
    asm volatile("ldmatrix.sync.aligned.m8n8.x4.shared.b16 {%0,%1,%2,%3}, [%4];"
        : "=r"(r[0]), "=r"(r[1]), "=r"(r[2]), "=r"(r[3]) : "r"(addr));
}
__device__ __forceinline__ void ldsm2(uint32_t* r, uint32_t addr) {
    asm volatile("ldmatrix.sync.aligned.m8n8.x2.shared.b16 {%0,%1}, [%2];"
        : "=r"(r[0]), "=r"(r[1]) : "r"(addr));
}
__device__ __forceinline__ void mma_bf16(float* d, const uint32_t* a, const uint32_t* b) {
    asm volatile(
        "mma.sync.aligned.m16n8k16.row.col.f32.bf16.bf16.f32 "
        "{%0,%1,%2,%3}, {%4,%5,%6,%7}, {%8,%9}, {%0,%1,%2,%3};"
        : "+f"(d[0]), "+f"(d[1]), "+f"(d[2]), "+f"(d[3])
        : "r"(a[0]), "r"(a[1]), "r"(a[2]), "r"(a[3]), "r"(b[0]), "r"(b[1]));
}

// ============================================================
// Prologue 1: inverse L2 norms of lut columns (fp32)
// ============================================================
__global__ void norm_kernel(const float* __restrict__ lut) {
    int n = blockIdx.x * blockDim.x + threadIdx.x;
    float s = 0.f;
#pragma unroll 8
    for (int d = 0; d < D; ++d) {
        float v = lut[(size_t)d * NREF + n];
        s = fmaf(v, v, s);
    }
    g_inv_rnorm[n] = 1.0f / sqrtf(s);
}

// ============================================================
// Prologue 2: P = W @ lut  (96 x 16384), fp32, 8 channels/thread
// ============================================================
__global__ void proj_lut_kernel(const float* __restrict__ lut,
                                const float* __restrict__ w) {
    int n  = blockIdx.x * 128 + threadIdx.x;
    int c0 = blockIdx.y * 8;
    float a[8] = {0, 0, 0, 0, 0, 0, 0, 0};
#pragma unroll 4
    for (int d = 0; d < D; ++d) {
        float l = lut[(size_t)d * NREF + n];
#pragma unroll
        for (int c = 0; c < 8; ++c)
            a[c] = fmaf(w[(c0 + c) * D + d], l, a[c]);
    }
#pragma unroll
    for (int c = 0; c < 8; ++c)
        g_P[(size_t)(c0 + c) * NREF + n] = a[c];
}

// ============================================================
// top-4 helpers (strict >: earliest/lowest index wins ties, matching jax)
// ============================================================
__device__ __forceinline__ void insert4(float* v, int* ix, float s, int n) {
    if (s > v[3]) {
        if (s > v[0]) {
            v[3]=v[2]; ix[3]=ix[2]; v[2]=v[1]; ix[2]=ix[1];
            v[1]=v[0]; ix[1]=ix[0]; v[0]=s;    ix[0]=n;
        } else if (s > v[1]) {
            v[3]=v[2]; ix[3]=ix[2]; v[2]=v[1]; ix[2]=ix[1];
            v[1]=s;    ix[1]=n;
        } else if (s > v[2]) {
            v[3]=v[2]; ix[3]=ix[2]; v[2]=s; ix[2]=n;
        } else { v[3]=s; ix[3]=n; }
    }
}
__device__ __forceinline__ void insert4u(unsigned long long* v, unsigned long long k) {
    if (k > v[3]) {
        if (k > v[0])      { v[3]=v[2]; v[2]=v[1]; v[1]=v[0]; v[0]=k; }
        else if (k > v[1]) { v[3]=v[2]; v[2]=v[1]; v[1]=k; }
        else if (k > v[2]) { v[3]=v[2]; v[2]=k; }
        else               { v[3]=k; }
    }
}

// ============================================================
// Exact 3-way bf16 decomposition of an fp32 pair, packed bf16x2.
// x = h + m + l exactly (24 mantissa bits = 3 x 8).
// ============================================================
__device__ __forceinline__ void split3_pair(float f0, float f1,
                                            uint32_t& hu, uint32_t& mu, uint32_t& lu) {
    uint32_t h0 = __float_as_uint(f0) & 0xFFFF0000u;
    uint32_t h1 = __float_as_uint(f1) & 0xFFFF0000u;
    hu = __byte_perm(h0, h1, 0x7632);
    float r10 = f0 - __uint_as_float(h0);      // exact
    float r11 = f1 - __uint_as_float(h1);
    uint32_t m0 = __float_as_uint(r10) & 0xFFFF0000u;
    uint32_t m1 = __float_as_uint(r11) & 0xFFFF0000u;
    mu = __byte_perm(m0, m1, 0x7632);
    float r20 = r10 - __uint_as_float(m0);     // exact, <=8 significant bits
    float r21 = r11 - __uint_as_float(m1);
    lu = __byte_perm(__float_as_uint(r20), __float_as_uint(r21), 0x7632);
}

// ============================================================
// Main: 512 threads, 16 warps (4M x 4N), warp tile 32x32.
// Round-12 bulk-sync KC64 pipeline (validated), doubled warps/SMSP for
// latency hiding; fused B ldsm4 (BH+BM in one instruction).
// ============================================================
__global__ __launch_bounds__(NTHREADS, 1)
void match_kernel(const float* __restrict__ x, const float* __restrict__ lut) {
    extern __shared__ __align__(16) char smraw[];
    uint32_t smb;
    asm("{ .reg .u64 t; cvta.to.shared.u64 t, %1; cvt.u32.u64 %0, t; }"
        : "=r"(smb) : "l"(smraw));

    const int tid  = threadIdx.x;
    const int lane = tid & 31;
    const int wid  = tid >> 5;
    const int wm   = wid >> 2;       // 0..3
    const int wn   = wid & 3;        // 0..3
    const int t0   = blockIdx.x * TM_CTA;
    const int nb0  = blockIdx.y * (NREF / NSPLIT);

    // conversion mapping: token/row ct (0..127), k-quarter ch (0..3)
    const int ct = tid & 127;
    const int ch = tid >> 7;

    // ldmatrix lane mappings (hardware-validated rounds 10-12)
    const int arow = lane & 15;
    const int akb  = lane >> 4;
    const int ar7  = arow & 7;
    const int l15  = lane & 15;               // fused-B addressing
    const int brow = l15 & 7;
    const int bkb  = (l15 >> 3) & 1;
    const uint32_t bBufOff = (lane < 16) ? SM_BH : SM_BM;   // lanes 16-31 -> BM
    const uint32_t aRowOff = (uint32_t)((wm * 32 + arow) * 128);
    const uint32_t bRowOff = (uint32_t)((wn * 32 + brow) * 128);

    float* Sn = (float*)(smraw + SM_SN);

    // running top-4 across all subtiles (owned by threads 0..127)
    float topv[4] = {NEG_INF, NEG_INF, NEG_INF, NEG_INF};
    int   topi[4] = {0, 0, 0, 0};

#pragma unroll 1
    for (int st = 0; st < SUBTILES; ++st) {
        const int nb = nb0 + st * TN_SUB;
        if (tid < TN_SUB) Sn[tid] = g_inv_rnorm[nb + tid];

        float acc[2][4][4];
#pragma unroll
        for (int mt = 0; mt < 2; ++mt)
#pragma unroll
            for (int nt = 0; nt < 4; ++nt)
#pragma unroll
                for (int q = 0; q < 4; ++q) acc[mt][nt][q] = 0.f;

        // ---- fp32 stage loader: A = x[kc*64.., t0..+128], B = lut[.., nb..+128]
        auto load_stage = [&](int kc) {
            const uint32_t dst = smb + SM_F32 + (uint32_t)(kc & 1) * SM_F32_STRIDE;
            const int d0 = kc * KC;
            const float* xs = x   + (size_t)d0 * T    + t0;
            const float* ls = lut + (size_t)d0 * NREF + nb;
#pragma unroll
            for (int i = 0; i < 4; ++i) {
                const int id = tid + i * NTHREADS;
                const int r = id >> 5, cq = id & 31;
                cpasync16(dst + (uint32_t)(r * 512 + cq * 16),
                          xs + (size_t)r * T + cq * 4);
            }
#pragma unroll
            for (int i = 0; i < 4; ++i) {
                const int id = tid + i * NTHREADS;
                const int r = id >> 5, cq = id & 31;
                cpasync16(dst + 32768u + (uint32_t)(r * 512 + cq * 16),
                          ls + (size_t)r * NREF + cq * 4);
            }
            cp_commit();
        };

        load_stage(0);

#pragma unroll 1
        for (int kc = 0; kc < NITER; ++kc) {
            if (kc + 1 < NITER) { load_stage(kc + 1); cp_wait<1>(); }
            else                { cp_wait<0>(); }
            __syncthreads();   // fp32(kc) ready; prior MMA done before bf16 overwrite

            // ---- exact split fp32 [k][row] -> bf16 h/m/l [row][k] (swizzled) ----
            // Each thread handles 2 of 8 chunks (conflict-free STS.128).
            {
                const float* Af = (const float*)(smraw + SM_F32 + (size_t)(kc & 1) * SM_F32_STRIDE);
                const float* Bf = Af + 8192;   // +32KB
#pragma unroll
                for (int cc = 0; cc < 2; ++cc) {
                    const int cl = ch * 2 + cc;            // chunk 0..7
                    const uint32_t pos = (uint32_t)(ct * 128 + ((cl ^ (ct & 7)) << 4));
                    uint32_t h[4], m[4], l[4];
#pragma unroll
                    for (int p = 0; p < 4; ++p) {
                        const int k = cl * 8 + 2 * p;
                        split3_pair(Af[k * 128 + ct], Af[(k + 1) * 128 + ct],
                                    h[p], m[p], l[p]);
                    }
                    *(uint4*)(smraw + SM_AH + pos) = make_uint4(h[0], h[1], h[2], h[3]);
                    *(uint4*)(smraw + SM_AM + pos) = make_uint4(m[0], m[1], m[2], m[3]);
                    *(uint4*)(smraw + SM_AL + pos) = make_uint4(l[0], l[1], l[2], l[3]);
#pragma unroll
                    for (int p = 0; p < 4; ++p) {
                        const int k = cl * 8 + 2 * p;
                        split3_pair(Bf[k * 128 + ct], Bf[(k + 1) * 128 + ct],
                                    h[p], m[p], l[p]);
                    }
                    *(uint4*)(smraw + SM_BH + pos) = make_uint4(h[0], h[1], h[2], h[3]);
                    *(uint4*)(smraw + SM_BM + pos) = make_uint4(m[0], m[1], m[2], m[3]);
                    *(uint4*)(smraw + SM_BL + pos) = make_uint4(l[0], l[1], l[2], l[3]);
                }
            }
            __syncthreads();   // bf16 ready

            // ---- 6-pass MMA per ks: B h/m fused-ldsm4 + l ldsm2, reg-cached ----
#pragma unroll
            for (int ks = 0; ks < 4; ++ks) {
                const uint32_t ac = (uint32_t)(((ks * 2 + akb) ^ ar7) * 16);
                const uint32_t bc = (uint32_t)(((ks * 2 + bkb) ^ brow) * 16);
                uint32_t a_op[2][4];
                uint32_t bhm[4][4], bl[4][2];

#pragma unroll
                for (int nt = 0; nt < 4; ++nt) {
                    ldsm4(bhm[nt], smb + bBufOff + bRowOff + nt * 1024 + bc);
                    ldsm2(bl[nt],  smb + SM_BL   + bRowOff + nt * 1024 + bc);
                }

                // A = h : hh, hm, hl
#pragma unroll
                for (int mt = 0; mt < 2; ++mt)
                    ldsm4(a_op[mt], smb + SM_AH + aRowOff + mt * 2048 + ac);
#pragma unroll
                for (int mt = 0; mt < 2; ++mt)
#pragma unroll
                    for (int nt = 0; nt < 4; ++nt)
                        mma_bf16(acc[mt][nt], a_op[mt], &bhm[nt][0]);
#pragma unroll
                for (int mt = 0; mt < 2; ++mt)
#pragma unroll
                    for (int nt = 0; nt < 4; ++nt)
                        mma_bf16(acc[mt][nt], a_op[mt], &bhm[nt][2]);
#pragma unroll
                for (int mt = 0; mt < 2; ++mt)
#pragma unroll
                    for (int nt = 0; nt < 4; ++nt)
                        mma_bf16(acc[mt][nt], a_op[mt], bl[nt]);

                // A = m : mh, mm
#pragma unroll
                for (int mt = 0; mt < 2; ++mt)
                    ldsm4(a_op[mt], smb + SM_AM + aRowOff + mt * 2048 + ac);
#pragma unroll
                for (int mt = 0; mt < 2; ++mt)
#pragma unroll
                    for (int nt = 0; nt < 4; ++nt)
                        mma_bf16(acc[mt][nt], a_op[mt], &bhm[nt][0]);
#pragma unroll
                for (int mt = 0; mt < 2; ++mt)
#pragma unroll
                    for (int nt = 0; nt < 4; ++nt)
                        mma_bf16(acc[mt][nt], a_op[mt], &bhm[nt][2]);

                // A = l : lh
#pragma unroll
                for (int mt = 0; mt < 2; ++mt)
                    ldsm4(a_op[mt], smb + SM_AL + aRowOff + mt * 2048 + ac);
#pragma unroll
                for (int mt = 0; mt < 2; ++mt)
#pragma unroll
                    for (int nt = 0; nt < 4; ++nt)
                        mma_bf16(acc[mt][nt], a_op[mt], &bhm[nt][0]);
            }
            __syncthreads();   // MMA on this stage done before bf16 reuse
        }

        // ---- subtile epilogue: scale + update running top-4 ----
        float* buf = (float*)smraw;            // reuse bf16 region: 128 x BUF_STRIDE
        const int r0 = wm * 32 + (lane >> 2);
        const int cb = wn * 32 + 2 * (lane & 3);
#pragma unroll
        for (int mt = 0; mt < 2; ++mt)
#pragma unroll
            for (int nt = 0; nt < 4; ++nt) {
                const int rr = r0 + mt * 16;
                const int cc = cb + nt * 8;
                const float s0 = Sn[cc], s1 = Sn[cc + 1];
                buf[rr * BUF_STRIDE + cc]           = acc[mt][nt][0] * s0;
                buf[rr * BUF_STRIDE + cc + 1]       = acc[mt][nt][1] * s1;
                buf[(rr + 8) * BUF_STRIDE + cc]     = acc[mt][nt][2] * s0;
                buf[(rr + 8) * BUF_STRIDE + cc + 1] = acc[mt][nt][3] * s1;
            }
        __syncthreads();

        if (tid < TM_CTA) {
            const float* row = buf + tid * BUF_STRIDE;
#pragma unroll 4
            for (int cc = 0; cc < TN_SUB; ++cc)
                insert4(topv, topi, row[cc], nb + cc);
        }
        __syncthreads();   // scan done before next subtile overwrites smem
    }

    // ---- final: 4 candidates per (token, split) ----
    if (tid < TM_CTA) {
        const size_t base = ((size_t)(t0 + tid) * NSPLIT + blockIdx.y) * 4;
#pragma unroll
        for (int j = 0; j < 4; ++j) {
            g_cand_val[base + j] = topv[j];
            g_cand_idx[base + j] = topi[j];
        }
    }
}

// ============================================================
// Merge 64 candidates/token -> top-4 (warp per token, u64 keys),
// then out[c,t] = 0.25 * sum_k P[c, idx_k] + b[c].
// grid T/4 blocks, 128 threads.
// ============================================================
__global__ __launch_bounds__(128, 1)
void merge_project_kernel(const float* __restrict__ bias,
                          float* __restrict__ out) {
    __shared__ int sel[4][4];
    const int w = threadIdx.x >> 5, lane = threadIdx.x & 31;
    const int t = blockIdx.x * 4 + w;

    const float* vb = g_cand_val + (size_t)t * CANDS;
    const int*   ib = g_cand_idx + (size_t)t * CANDS;

    unsigned long long best[4] = {0, 0, 0, 0};
#pragma unroll
    for (int j = 0; j < CANDS / 32; ++j) {
        const int e = lane + j * 32;
        uint32_t u = __float_as_uint(vb[e]);
        u ^= (u & 0x80000000u) ? 0xFFFFFFFFu : 0x80000000u;
        unsigned long long key =
            ((unsigned long long)u << 32) | (uint32_t)(0x7FFFFFFF - ib[e]);
        insert4u(best, key);
    }
#pragma unroll
    for (int off = 16; off; off >>= 1) {
        unsigned long long o0 = __shfl_xor_sync(0xFFFFFFFFu, best[0], off);
        unsigned long long o1 = __shfl_xor_sync(0xFFFFFFFFu, best[1], off);
        unsigned long long o2 = __shfl_xor_sync(0xFFFFFFFFu, best[2], off);
        unsigned long long o3 = __shfl_xor_sync(0xFFFFFFFFu, best[3], off);
        insert4u(best, o0); insert4u(best, o1);
        insert4u(best, o2); insert4u(best, o3);
    }
    if (lane < 4) sel[w][lane] = 0x7FFFFFFF - (int)(uint32_t)best[lane];
    __syncthreads();

    for (int i = threadIdx.x; i < 4 * C; i += 128) {
        const int cch = i % C;
        const int tw  = i / C;
        const float* Pr = g_P + (size_t)cch * NREF;
        const int* s = sel[tw];
        float o = 0.25f * (Pr[s[0]] + Pr[s[1]] + Pr[s[2]] + Pr[s[3]]);
        out[(size_t)cch * T + (blockIdx.x * 4 + tw)] = o + bias[cch];
    }
}

// ============================================================
extern "C" void kernel_launch(void* const* d_in, const int* in_sizes, int n_in,
                              void* d_out, int out_size) {
    const float* x    = (const float*)d_in[0];   // [1, 768, 8192]
    const float* lut  = (const float*)d_in[1];   // [1, 768, 16384]
    const float* w    = (const float*)d_in[2];   // [96, 768]
    const float* bias = (const float*)d_in[3];   // [96]
    float* out = (float*)d_out;                  // [1, 96, 8192]

    cudaFuncSetAttribute(match_kernel,
                         cudaFuncAttributeMaxDynamicSharedMemorySize,
                         SMEM_BYTES);

    norm_kernel<<<NREF / 256, 256>>>(lut);
    proj_lut_kernel<<<dim3(NREF / 128, C / 8), 128>>>(lut, w);
    match_kernel<<<dim3(TTILES, NSPLIT), NTHREADS, SMEM_BYTES>>>(x, lut);
    merge_project_kernel<<<T / 4, 128>>>(bias, out);
}